// round 6
// baseline (speedup 1.0000x reference)
#include <cuda_runtime.h>
#include <cuda_bf16.h>
#include <cstdint>

#define KK 6144
#define BB 256
#define NITER 6

// ---------------- scratch (static __device__ — no allocations) ----------------
__device__ float4 g_W[KK * BB];            // per-step edge weights {wa, wb, wnb, wna}
__device__ float4 g_alpha[KK * BB * 2];    // alpha_k, 8 floats per (k,b)
__device__ float4 g_beta[KK * BB * 2];     // beta_{k+1}, 8 floats per (k,b)
__device__ float  g_ls1[KK * BB];
__device__ float  g_lp1[KK * BB];
__device__ float  g_lp2[KK * BB];
__device__ float  g_ls2[KK * BB];
__device__ float  g_la2[KK * BB];
__device__ float  g_le1[KK * BB];
__device__ float  g_le2[KK * BB];          // extrinsic from decoder 2 = a-priori for decoder 1

// ---------------- FMA-pipe exp/log (no MUFU) ----------------
__device__ __forceinline__ float fexp(float x) {
    // exp(x) for x <= 0 (weights are shifted so args are non-positive); clamp for range safety
    x = fmaxf(x, -80.0f);
    float t  = fmaf(x, 1.4426950408889634f, 12582912.0f);   // round(x*log2e) via magic number
    int   ir = __float_as_int(t) - 0x4B400000;              // integer part
    float r  = t - 12582912.0f;
    float f  = fmaf(x, 1.4426950408889634f, -r);            // fractional part in [-0.5, 0.5]
    float p  = 1.5403530393e-4f;
    p = fmaf(p, f, 1.3333558146e-3f);
    p = fmaf(p, f, 9.6181291076e-3f);
    p = fmaf(p, f, 5.5504108664e-2f);
    p = fmaf(p, f, 2.4022650696e-1f);
    p = fmaf(p, f, 6.9314718056e-1f);
    p = fmaf(p, f, 1.0f);
    return __int_as_float(__float_as_int(p) + (ir << 23));  // scale by 2^ir (exact)
}

__device__ __forceinline__ float flog(float x) {
    // natural log for positive normal floats (cephes-style)
    int bits = __float_as_int(x);
    int e    = (bits >> 23) - 126;                                   // mant in [0.5, 1)
    float mant = __int_as_float((bits & 0x007FFFFF) | 0x3F000000);
    if (mant < 0.70710678f) { e -= 1; mant += mant; }                // mant in [0.7071, 1.4142)
    float z  = mant - 1.0f;
    float zz = z * z;
    float p  = 7.0376836292e-2f;
    p = fmaf(p, z, -1.1514610310e-1f);
    p = fmaf(p, z,  1.1676998740e-1f);
    p = fmaf(p, z, -1.2420140846e-1f);
    p = fmaf(p, z,  1.4249322787e-1f);
    p = fmaf(p, z, -1.6668057665e-1f);
    p = fmaf(p, z,  2.0000714765e-1f);
    p = fmaf(p, z, -2.4999993993e-1f);
    p = fmaf(p, z,  3.3333331174e-1f);
    float y = fmaf(p * z, zz, -0.5f * zz);
    return fmaf((float)e, 0.69314718056f, z + y);
}

// ---------------- setup: deinterleave & negate channel LLRs ----------------
__global__ void k_deint(const float* __restrict__ in) {
    int idx = blockIdx.x * 256 + threadIdx.x;       // idx = b*KK + k
    int k = idx % KK, b = idx / KK;
    const float* p = in + (size_t)b * (3 * KK) + 3 * k;
    float v0 = p[0], v1 = p[1], v2 = p[2];
    g_ls1[k * BB + b] = -v0;
    g_lp1[k * BB + b] = -v1;
    g_lp2[k * BB + b] = -v2;
}

__global__ void k_mkls2(const int* __restrict__ perm) {
    int idx = blockIdx.x * 256 + threadIdx.x;       // idx = j*BB + b
    int b = idx & (BB - 1), j = idx >> 8;
    g_ls2[idx] = g_ls1[perm[j] * BB + b];
    g_le2[idx] = 0.0f;
}

// ---------------- prep: gamma exponentials (and a-priori gather for dec 2) ----------------
__global__ void k_prep(int dec, const int* __restrict__ perm) {
    int idx = blockIdx.x * 256 + threadIdx.x;       // idx = k*BB + b
    int b = idx & (BB - 1), k = idx >> 8;
    float la, lsv, lpv;
    if (dec == 1) {
        la  = g_le2[idx];
        lsv = g_ls1[idx];
        lpv = g_lp1[idx];
    } else {
        la  = g_le1[perm[k] * BB + b];
        g_la2[idx] = la;
        lsv = g_ls2[idx];
        lpv = g_lp2[idx];
    }
    float lsu = lsv + la;
    float ga = 0.5f * (lsu + lpv);
    float gb = 0.5f * (lsu - lpv);
    float m  = fmaxf(fabsf(ga), fabsf(gb));
    g_W[idx] = make_float4(fexp(ga - m), fexp(gb - m), fexp(-gb - m), fexp(-ga - m));
}

// ---------------- scan: forward alpha + backward beta recursions ----------------
// blocks 0..7: forward chains (b = blk*32+lane); blocks 8..15: backward.
// Power-of-two renorm folded into the NEXT step's weights -> alpha->alpha path = 2 FMA.
__global__ void __launch_bounds__(32, 1) k_scan() {
    int t = threadIdx.x;
    int blk = blockIdx.x;
    if (blk < 8) {
        int b = blk * 32 + t;
        const float4* Wp = g_W + b;
        float4* Ap = g_alpha + 2 * b;
        float a0 = 1.f, a1 = 0.f, a2 = 0.f, a3 = 0.f, a4 = 0.f, a5 = 0.f, a6 = 0.f, a7 = 0.f;
        float sc = 1.f;
        float4 w[8];
#pragma unroll
        for (int i = 0; i < 8; i++) w[i] = Wp[(size_t)i * BB];
#pragma unroll 1
        for (int k = 0; k < KK; k += 8) {
#pragma unroll
            for (int i = 0; i < 8; i++) {
                float4 W = w[i];
                int nk = k + 8 + i; nk = (nk < KK) ? nk : (KK - 1);
                w[i] = Wp[(size_t)nk * BB];
                size_t off = (size_t)(k + i) * (BB * 2);
                Ap[off]     = make_float4(a0, a1, a2, a3);
                Ap[off + 1] = make_float4(a4, a5, a6, a7);
                float wa = W.x * sc, wb = W.y * sc, wnb = W.z * sc, wna = W.w * sc;
                float n0 = fmaf(a0, wa,  a1 * wna);
                float n1 = fmaf(a2, wnb, a3 * wb);
                float n2 = fmaf(a4, wb,  a5 * wnb);
                float n3 = fmaf(a6, wna, a7 * wa);
                float n4 = fmaf(a0, wna, a1 * wa);
                float n5 = fmaf(a2, wb,  a3 * wnb);
                float n6 = fmaf(a4, wnb, a5 * wb);
                float n7 = fmaf(a6, wa,  a7 * wna);
                float m = fmaxf(fmaxf(fmaxf(n0, n1), fmaxf(n2, n3)),
                                fmaxf(fmaxf(n4, n5), fmaxf(n6, n7)));
                sc = __int_as_float(0x7F000000 - (__float_as_int(m) & 0x7F800000)); // 2^-E(m)
                a0 = n0; a1 = n1; a2 = n2; a3 = n3; a4 = n4; a5 = n5; a6 = n6; a7 = n7;
            }
        }
    } else {
        int b = (blk - 8) * 32 + t;
        const float4* Wp = g_W + b;
        float4* Bp = g_beta + 2 * b;
        float b0 = 1.f, b1 = 1.f, b2 = 1.f, b3 = 1.f, b4 = 1.f, b5 = 1.f, b6 = 1.f, b7 = 1.f;
        float sc = 1.f;
        float4 w[8];
#pragma unroll
        for (int i = 0; i < 8; i++) w[i] = Wp[(size_t)(KK - 1 - i) * BB];
#pragma unroll 1
        for (int k = 0; k < KK; k += 8) {
#pragma unroll
            for (int i = 0; i < 8; i++) {
                int kk = KK - 1 - (k + i);
                float4 W = w[i];
                int pk = KK - 1 - (k + 8 + i); pk = (pk > 0) ? pk : 0;
                w[i] = Wp[(size_t)pk * BB];
                size_t off = (size_t)kk * (BB * 2);
                Bp[off]     = make_float4(b0, b1, b2, b3);   // this is beta_{kk+1}
                Bp[off + 1] = make_float4(b4, b5, b6, b7);
                float wa = W.x * sc, wb = W.y * sc, wnb = W.z * sc, wna = W.w * sc;
                float n0 = fmaf(wa, b0, wna * b4);
                float n1 = fmaf(wa, b4, wna * b0);
                float n2 = fmaf(wb, b5, wnb * b1);
                float n3 = fmaf(wb, b1, wnb * b5);
                float n4 = fmaf(wb, b2, wnb * b6);
                float n5 = fmaf(wb, b6, wnb * b2);
                float n6 = fmaf(wa, b7, wna * b3);
                float n7 = fmaf(wa, b3, wna * b7);
                float m = fmaxf(fmaxf(fmaxf(n0, n1), fmaxf(n2, n3)),
                                fmaxf(fmaxf(n4, n5), fmaxf(n6, n7)));
                sc = __int_as_float(0x7F000000 - (__float_as_int(m) & 0x7F800000));
                b0 = n0; b1 = n1; b2 = n2; b3 = n3; b4 = n4; b5 = n5; b6 = n6; b7 = n7;
            }
        }
    }
}

// ---------------- post: posterior LLR + extrinsic (+ interleave scatter / output) ----------------
__global__ void k_post(int dec, const int* __restrict__ perm,
                       float* __restrict__ outp, int wout) {
    int idx = blockIdx.x * 256 + threadIdx.x;       // idx = k*BB + b
    int b = idx & (BB - 1), k = idx >> 8;
    float4 A1 = g_alpha[idx * 2],   A2 = g_alpha[idx * 2 + 1];   // alpha 0..3, 4..7
    float4 B1 = g_beta[idx * 2],    B2 = g_beta[idx * 2 + 1];    // beta  0..3, 4..7
    float4 W  = g_W[idx];                                        // wa, wb, wnb, wna
    // u=0 edges: (wa: 0->0, 1->4, 6->7, 7->3) (wb: 2->5, 3->1, 4->2, 5->6)
    float s0a = fmaf(A1.x, B1.x, fmaf(A1.y, B2.x, fmaf(A2.z, B2.w, A2.w * B1.w)));
    float s0b = fmaf(A1.z, B2.y, fmaf(A1.w, B1.y, fmaf(A2.x, B1.z, A2.y * B2.z)));
    // u=1 edges: (wna: 0->4, 1->0, 6->3, 7->7) (wnb: 2->1, 3->5, 4->6, 5->2)
    float s1a = fmaf(A1.x, B2.x, fmaf(A1.y, B1.x, fmaf(A2.z, B1.w, A2.w * B2.w)));
    float s1b = fmaf(A1.z, B1.y, fmaf(A1.w, B2.y, fmaf(A2.x, B2.z, A2.y * B1.z)));
    float S0 = fmaf(W.x, s0a, W.y * s0b);
    float S1 = fmaf(W.w, s1a, W.z * s1b);
    float lpost = flog(fmaxf(S0, 1e-37f)) - flog(fmaxf(S1, 1e-37f));
    if (dec == 1) {
        g_le1[idx] = lpost - g_le2[idx] - g_ls1[idx];
    } else {
        float ext = lpost - g_la2[idx] - g_ls2[idx];
        int pk = perm[k];
        g_le2[pk * BB + b] = ext;                    // = (lpost2-la2-ls2)[:, inv]
        if (wout) outp[(size_t)b * KK + pk] = -lpost; // = -lpost2[:, inv]
    }
}

// ---------------- launch ----------------
extern "C" void kernel_launch(void* const* d_in, const int* in_sizes, int n_in,
                              void* d_out, int out_size) {
    const float* in  = (const float*)d_in[0];
    const int* perm  = (const int*)d_in[1];
    if (n_in >= 2 && in_sizes[0] == KK && in_sizes[1] != KK) {   // defensive: swapped order
        in   = (const float*)d_in[1];
        perm = (const int*)d_in[0];
    }
    const int NB = (KK * BB) / 256;   // 6144 blocks of 256 threads

    k_deint<<<NB, 256>>>(in);
    k_mkls2<<<NB, 256>>>(perm);

    for (int it = 0; it < NITER; it++) {
        // decoder 1
        k_prep<<<NB, 256>>>(1, perm);
        k_scan<<<16, 32>>>();
        k_post<<<NB, 256>>>(1, perm, (float*)d_out, 0);
        // decoder 2
        k_prep<<<NB, 256>>>(2, perm);
        k_scan<<<16, 32>>>();
        k_post<<<NB, 256>>>(2, perm, (float*)d_out, (it == NITER - 1) ? 1 : 0);
    }
}

// round 7
// speedup vs baseline: 3.4626x; 3.4626x over previous
#include <cuda_runtime.h>
#include <cuda_bf16.h>
#include <cstdint>

#define KK 6144
#define BB 256
#define NITER 6
#define CH 128                  // stored chunk length
#define WU 256                  // warm-up length
#define NCH (KK / CH)           // 48 chunks

// ---------------- scratch (static __device__ — no allocations) ----------------
__device__ float4 g_W[KK * BB];            // per-step edge weights {wa, wb, wnb, wna}
__device__ float4 g_alpha[KK * BB * 2];    // alpha_k, 8 floats per (k,b)
__device__ float  g_ls1[KK * BB];
__device__ float  g_lp1[KK * BB];
__device__ float  g_lp2[KK * BB];
__device__ float  g_ls2[KK * BB];
__device__ float  g_la2[KK * BB];
__device__ float  g_le1[KK * BB];
__device__ float  g_le2[KK * BB];          // extrinsic from decoder 2 = a-priori for decoder 1

// ---------------- FMA-pipe exp/log (no MUFU) ----------------
__device__ __forceinline__ float fexp(float x) {
    x = fmaxf(x, -80.0f);
    float t  = fmaf(x, 1.4426950408889634f, 12582912.0f);
    int   ir = __float_as_int(t) - 0x4B400000;
    float r  = t - 12582912.0f;
    float f  = fmaf(x, 1.4426950408889634f, -r);
    float p  = 1.5403530393e-4f;
    p = fmaf(p, f, 1.3333558146e-3f);
    p = fmaf(p, f, 9.6181291076e-3f);
    p = fmaf(p, f, 5.5504108664e-2f);
    p = fmaf(p, f, 2.4022650696e-1f);
    p = fmaf(p, f, 6.9314718056e-1f);
    p = fmaf(p, f, 1.0f);
    return __int_as_float(__float_as_int(p) + (ir << 23));
}

__device__ __forceinline__ float flog(float x) {
    int bits = __float_as_int(x);
    int e    = (bits >> 23) - 126;
    float mant = __int_as_float((bits & 0x007FFFFF) | 0x3F000000);
    if (mant < 0.70710678f) { e -= 1; mant += mant; }
    float z  = mant - 1.0f;
    float zz = z * z;
    float p  = 7.0376836292e-2f;
    p = fmaf(p, z, -1.1514610310e-1f);
    p = fmaf(p, z,  1.1676998740e-1f);
    p = fmaf(p, z, -1.2420140846e-1f);
    p = fmaf(p, z,  1.4249322787e-1f);
    p = fmaf(p, z, -1.6668057665e-1f);
    p = fmaf(p, z,  2.0000714765e-1f);
    p = fmaf(p, z, -2.4999993993e-1f);
    p = fmaf(p, z,  3.3333331174e-1f);
    float y = fmaf(p * z, zz, -0.5f * zz);
    return fmaf((float)e, 0.69314718056f, z + y);
}

// ---------------- setup: deinterleave & negate channel LLRs ----------------
__global__ void k_deint(const float* __restrict__ in) {
    int idx = blockIdx.x * 256 + threadIdx.x;       // idx = b*KK + k
    int k = idx % KK, b = idx / KK;
    const float* p = in + (size_t)b * (3 * KK) + 3 * k;
    float v0 = p[0], v1 = p[1], v2 = p[2];
    g_ls1[k * BB + b] = -v0;
    g_lp1[k * BB + b] = -v1;
    g_lp2[k * BB + b] = -v2;
}

__global__ void k_mkls2(const int* __restrict__ perm) {
    int idx = blockIdx.x * 256 + threadIdx.x;       // idx = j*BB + b
    int b = idx & (BB - 1), j = idx >> 8;
    g_ls2[idx] = g_ls1[perm[j] * BB + b];
    g_le2[idx] = 0.0f;
}

// ---------------- prep: gamma exponentials (and a-priori gather for dec 2) ----------------
__global__ void k_prep(int dec, const int* __restrict__ perm) {
    int idx = blockIdx.x * 256 + threadIdx.x;       // idx = k*BB + b
    int b = idx & (BB - 1), k = idx >> 8;
    float la, lsv, lpv;
    if (dec == 1) {
        la  = g_le2[idx];
        lsv = g_ls1[idx];
        lpv = g_lp1[idx];
    } else {
        la  = g_le1[perm[k] * BB + b];
        g_la2[idx] = la;
        lsv = g_ls2[idx];
        lpv = g_lp2[idx];
    }
    float lsu = lsv + la;
    float ga = 0.5f * (lsu + lpv);
    float gb = 0.5f * (lsu - lpv);
    float m  = fmaxf(fabsf(ga), fabsf(gb));
    g_W[idx] = make_float4(fexp(ga - m), fexp(gb - m), fexp(-gb - m), fexp(-ga - m));
}

// one forward trellis step (update a0..a7 with scaled weights, then renorm factor sc)
#define STEP_FWD(W)                                                               \
    {                                                                             \
        float wa = (W).x * sc, wb = (W).y * sc, wnb = (W).z * sc, wna = (W).w * sc;\
        float n0 = fmaf(a0, wa,  a1 * wna);                                       \
        float n1 = fmaf(a2, wnb, a3 * wb);                                        \
        float n2 = fmaf(a4, wb,  a5 * wnb);                                       \
        float n3 = fmaf(a6, wna, a7 * wa);                                        \
        float n4 = fmaf(a0, wna, a1 * wa);                                        \
        float n5 = fmaf(a2, wb,  a3 * wnb);                                       \
        float n6 = fmaf(a4, wnb, a5 * wb);                                        \
        float n7 = fmaf(a6, wa,  a7 * wna);                                       \
        float m = fmaxf(fmaxf(fmaxf(n0, n1), fmaxf(n2, n3)),                      \
                        fmaxf(fmaxf(n4, n5), fmaxf(n6, n7)));                     \
        sc = __int_as_float(0x7F000000 - (__float_as_int(m) & 0x7F800000));       \
        a0 = n0; a1 = n1; a2 = n2; a3 = n3; a4 = n4; a5 = n5; a6 = n6; a7 = n7;   \
    }

// one backward trellis step
#define STEP_BWD(W)                                                               \
    {                                                                             \
        float wa = (W).x * sc, wb = (W).y * sc, wnb = (W).z * sc, wna = (W).w * sc;\
        float n0 = fmaf(wa, b0, wna * b4);                                        \
        float n1 = fmaf(wa, b4, wna * b0);                                        \
        float n2 = fmaf(wb, b5, wnb * b1);                                        \
        float n3 = fmaf(wb, b1, wnb * b5);                                        \
        float n4 = fmaf(wb, b2, wnb * b6);                                        \
        float n5 = fmaf(wb, b6, wnb * b2);                                        \
        float n6 = fmaf(wa, b7, wna * b3);                                        \
        float n7 = fmaf(wa, b3, wna * b7);                                        \
        float m = fmaxf(fmaxf(fmaxf(n0, n1), fmaxf(n2, n3)),                      \
                        fmaxf(fmaxf(n4, n5), fmaxf(n6, n7)));                     \
        sc = __int_as_float(0x7F000000 - (__float_as_int(m) & 0x7F800000));       \
        b0 = n0; b1 = n1; b2 = n2; b3 = n3; b4 = n4; b5 = n5; b6 = n6; b7 = n7;   \
    }

// ---------------- forward windowed scan: stores alpha for [cbase, cbase+CH) ----------------
__global__ void __launch_bounds__(32, 1) k_fwd() {
    int chunk = blockIdx.x >> 3;
    int b = ((blockIdx.x & 7) << 5) | threadIdx.x;
    int cbase = chunk * CH;
    int kbeg  = cbase - WU; if (kbeg < 0) kbeg = 0;
    int kend  = cbase + CH;
    const float4* Wp = g_W + b;
    float4* Ap = g_alpha + 2 * b;

    float a0, a1, a2, a3, a4, a5, a6, a7;
    if (kbeg == 0) {            // exact initial condition: state 0
        a0 = 1.f; a1 = a2 = a3 = a4 = a5 = a6 = a7 = 0.f;
    } else {                    // warm-up from uniform
        a0 = a1 = a2 = a3 = a4 = a5 = a6 = a7 = 1.f;
    }
    float sc = 1.f;

    float4 w[8];
#pragma unroll
    for (int i = 0; i < 8; i++) w[i] = Wp[(size_t)(kbeg + i) * BB];

    // warm-up (no stores); length is a multiple of 8
#pragma unroll 1
    for (int k = kbeg; k < cbase; k += 8) {
#pragma unroll
        for (int i = 0; i < 8; i++) {
            float4 W = w[i];
            int nk = k + 8 + i; nk = (nk < kend) ? nk : (kend - 1);
            w[i] = Wp[(size_t)nk * BB];
            STEP_FWD(W);
        }
    }
    // steady state: store alpha_k then advance
#pragma unroll 1
    for (int k = cbase; k < kend; k += 8) {
#pragma unroll
        for (int i = 0; i < 8; i++) {
            float4 W = w[i];
            int nk = k + 8 + i; nk = (nk < kend) ? nk : (kend - 1);
            w[i] = Wp[(size_t)nk * BB];
            size_t off = (size_t)(k + i) * (BB * 2);
            Ap[off]     = make_float4(a0, a1, a2, a3);
            Ap[off + 1] = make_float4(a4, a5, a6, a7);
            STEP_FWD(W);
        }
    }
}

// ---------------- backward windowed scan fused with posterior/extrinsic ----------------
__global__ void __launch_bounds__(32, 1) k_bwdpost(int dec, const int* __restrict__ perm,
                                                   float* __restrict__ outp, int wout) {
    int chunk = blockIdx.x >> 3;
    int b = ((blockIdx.x & 7) << 5) | threadIdx.x;
    int cbase = chunk * CH;
    int cend  = cbase + CH;                 // post emitted for k in [cbase, cend)
    int kend  = cend + WU; if (kend > KK) kend = KK;   // exclusive top (uniform init exact at KK)
    const float4* Wp = g_W + b;
    const float4* Ap = g_alpha + 2 * b;

    float b0 = 1.f, b1 = 1.f, b2 = 1.f, b3 = 1.f, b4 = 1.f, b5 = 1.f, b6 = 1.f, b7 = 1.f;
    float sc = 1.f;

    float4 w[8];
#pragma unroll
    for (int i = 0; i < 8; i++) {
        int kk = kend - 1 - i; kk = (kk >= cbase) ? kk : cbase;
        w[i] = Wp[(size_t)kk * BB];
    }

    // warm-up: k = kend-1 .. cend (length multiple of 8, possibly 0)
#pragma unroll 1
    for (int k = kend - 1; k >= cend; k -= 8) {
#pragma unroll
        for (int i = 0; i < 8; i++) {
            int kk = k - i;
            float4 W = w[i];
            int pk = kk - 8; pk = (pk >= cbase) ? pk : cbase;
            w[i] = Wp[(size_t)pk * BB];
            STEP_BWD(W);
        }
    }
    // steady: k = cend-1 .. cbase ; regs hold beta_{kk+1} at top of each step
#pragma unroll 1
    for (int k = cend - 1; k >= cbase; k -= 8) {
#pragma unroll
        for (int i = 0; i < 8; i++) {
            int kk = k - i;
            float4 W = w[i];
            int pk = kk - 8; pk = (pk >= cbase) ? pk : cbase;
            w[i] = Wp[(size_t)pk * BB];

            // posterior at kk: alpha_kk (loaded), beta_{kk+1} (regs), raw W (scales cancel)
            size_t off = (size_t)kk * (BB * 2);
            float4 A1 = Ap[off];
            float4 A2 = Ap[off + 1];
            float s0a = fmaf(A1.x, b0, fmaf(A1.y, b4, fmaf(A2.z, b7, A2.w * b3)));
            float s0b = fmaf(A1.z, b5, fmaf(A1.w, b1, fmaf(A2.x, b2, A2.y * b6)));
            float s1a = fmaf(A1.x, b4, fmaf(A1.y, b0, fmaf(A2.z, b3, A2.w * b7)));
            float s1b = fmaf(A1.z, b1, fmaf(A1.w, b5, fmaf(A2.x, b6, A2.y * b2)));
            float S0 = fmaf(W.x, s0a, W.y * s0b);
            float S1 = fmaf(W.w, s1a, W.z * s1b);
            float lpost = flog(fmaxf(S0, 1e-37f)) - flog(fmaxf(S1, 1e-37f));

            int idx = kk * BB + b;
            if (dec == 1) {
                g_le1[idx] = lpost - g_le2[idx] - g_ls1[idx];
            } else {
                float ext = lpost - g_la2[idx] - g_ls2[idx];
                int pkm = perm[kk];
                g_le2[pkm * BB + b] = ext;                       // = (lpost2-la2-ls2)[:, inv]
                if (wout) outp[(size_t)b * KK + pkm] = -lpost;   // = -lpost2[:, inv]
            }

            STEP_BWD(W);
        }
    }
}

// ---------------- launch ----------------
extern "C" void kernel_launch(void* const* d_in, const int* in_sizes, int n_in,
                              void* d_out, int out_size) {
    const float* in  = (const float*)d_in[0];
    const int* perm  = (const int*)d_in[1];
    if (n_in >= 2 && in_sizes[0] == KK && in_sizes[1] != KK) {   // defensive: swapped order
        in   = (const float*)d_in[1];
        perm = (const int*)d_in[0];
    }
    const int NB = (KK * BB) / 256;       // 6144 blocks of 256 threads
    const int NSCAN = NCH * 8;            // 384 blocks of 32 threads

    k_deint<<<NB, 256>>>(in);
    k_mkls2<<<NB, 256>>>(perm);

    for (int it = 0; it < NITER; it++) {
        // decoder 1
        k_prep<<<NB, 256>>>(1, perm);
        k_fwd<<<NSCAN, 32>>>();
        k_bwdpost<<<NSCAN, 32>>>(1, perm, (float*)d_out, 0);
        // decoder 2
        k_prep<<<NB, 256>>>(2, perm);
        k_fwd<<<NSCAN, 32>>>();
        k_bwdpost<<<NSCAN, 32>>>(2, perm, (float*)d_out, (it == NITER - 1) ? 1 : 0);
    }
}

// round 11
// speedup vs baseline: 13.0273x; 3.7623x over previous
#include <cuda_runtime.h>
#include <cuda_bf16.h>
#include <cstdint>

#define KK 6144
#define BB 256
#define NITER 6
#define CH 48                   // stored chunk length (48*8*32*4 = 48KB smem)
#define WU 64                   // warm-up length (multiple of 8)
#define NCH (KK / CH)           // 128 chunks

// ---------------- scratch (static __device__ — no allocations) ----------------
__device__ float4 g_W[KK * BB];            // per-step edge weights {wa, wb, wnb, wna}
__device__ float  g_ls1[KK * BB];
__device__ float  g_lp1[KK * BB];
__device__ float  g_lp2[KK * BB];
__device__ float  g_ls2[KK * BB];
__device__ float  g_la1[KK * BB];
__device__ float  g_la2[KK * BB];
__device__ float  g_lpost1[KK * BB];
__device__ float  g_lpost2[KK * BB];
__device__ int    g_inv[KK];

// ---------------- FMA-pipe exp/log (no MUFU) ----------------
__device__ __forceinline__ float fexp(float x) {
    x = fmaxf(x, -80.0f);
    float t  = fmaf(x, 1.4426950408889634f, 12582912.0f);
    int   ir = __float_as_int(t) - 0x4B400000;
    float r  = t - 12582912.0f;
    float f  = fmaf(x, 1.4426950408889634f, -r);
    float p  = 1.5403530393e-4f;
    p = fmaf(p, f, 1.3333558146e-3f);
    p = fmaf(p, f, 9.6181291076e-3f);
    p = fmaf(p, f, 5.5504108664e-2f);
    p = fmaf(p, f, 2.4022650696e-1f);
    p = fmaf(p, f, 6.9314718056e-1f);
    p = fmaf(p, f, 1.0f);
    return __int_as_float(__float_as_int(p) + (ir << 23));
}

__device__ __forceinline__ float flog(float x) {
    int bits = __float_as_int(x);
    int e    = (bits >> 23) - 126;
    float mant = __int_as_float((bits & 0x007FFFFF) | 0x3F000000);
    if (mant < 0.70710678f) { e -= 1; mant += mant; }
    float z  = mant - 1.0f;
    float zz = z * z;
    float p  = 7.0376836292e-2f;
    p = fmaf(p, z, -1.1514610310e-1f);
    p = fmaf(p, z,  1.1676998740e-1f);
    p = fmaf(p, z, -1.2420140846e-1f);
    p = fmaf(p, z,  1.4249322787e-1f);
    p = fmaf(p, z, -1.6668057665e-1f);
    p = fmaf(p, z,  2.0000714765e-1f);
    p = fmaf(p, z, -2.4999993993e-1f);
    p = fmaf(p, z,  3.3333331174e-1f);
    float y = fmaf(p * z, zz, -0.5f * zz);
    return fmaf((float)e, 0.69314718056f, z + y);
}

// ---------------- setup ----------------
__global__ void k_deint(const float* __restrict__ in) {
    int idx = blockIdx.x * 256 + threadIdx.x;       // idx = b*KK + k
    int k = idx % KK, b = idx / KK;
    const float* p = in + (size_t)b * (3 * KK) + 3 * k;
    float v0 = p[0], v1 = p[1], v2 = p[2];
    g_ls1[k * BB + b] = -v0;
    g_lp1[k * BB + b] = -v1;
    g_lp2[k * BB + b] = -v2;
}

__global__ void k_inv(const int* __restrict__ perm) {
    int j = blockIdx.x * 256 + threadIdx.x;
    if (j < KK) g_inv[perm[j]] = j;
}

// ls2 = ls1[perm], la2 = 0, lpost2 = ls2  (=> first la1 = lpost2-la2-ls2 = 0)
__global__ void k_init2(const int* __restrict__ perm) {
    int idx = blockIdx.x * 256 + threadIdx.x;       // idx = j*BB + b
    int b = idx & (BB - 1), j = idx >> 8;
    float v = g_ls1[perm[j] * BB + b];
    g_ls2[idx] = v;
    g_la2[idx] = 0.0f;
    g_lpost2[idx] = v;
}

// ---------------- prep: a-priori reconstruction + gamma exponentials ----------------
__device__ __forceinline__ void write_W(int idx, float lsu, float lpv) {
    float ga = 0.5f * (lsu + lpv);
    float gb = 0.5f * (lsu - lpv);
    float m  = fmaxf(fabsf(ga), fabsf(gb));
    g_W[idx] = make_float4(fexp(ga - m), fexp(gb - m), fexp(-gb - m), fexp(-ga - m));
}

__global__ void k_prep1() {                          // build W for decoder 1
    int idx = blockIdx.x * 256 + threadIdx.x;       // idx = k*BB + b
    int b = idx & (BB - 1), k = idx >> 8;
    int jb = g_inv[k] * BB + b;
    float la = g_lpost2[jb] - g_la2[jb] - g_ls2[jb]; // le2_de[k] = X[inv[k]]
    g_la1[idx] = la;
    write_W(idx, g_ls1[idx] + la, g_lp1[idx]);
}

__global__ void k_prep2(const int* __restrict__ perm) { // build W for decoder 2
    int idx = blockIdx.x * 256 + threadIdx.x;       // idx = j*BB + b
    int b = idx & (BB - 1), j = idx >> 8;
    int kb = perm[j] * BB + b;
    float la = g_lpost1[kb] - g_la1[kb] - g_ls1[kb]; // la2[j] = le1[perm[j]]
    g_la2[idx] = la;
    write_W(idx, g_ls2[idx] + la, g_lp2[idx]);
}

// ---------------- trellis steps ----------------
#define STEP_FWD(W)                                                               \
    {                                                                             \
        float wa = (W).x * sc, wb = (W).y * sc, wnb = (W).z * sc, wna = (W).w * sc;\
        float n0 = fmaf(a0, wa,  a1 * wna);                                       \
        float n1 = fmaf(a2, wnb, a3 * wb);                                        \
        float n2 = fmaf(a4, wb,  a5 * wnb);                                       \
        float n3 = fmaf(a6, wna, a7 * wa);                                        \
        float n4 = fmaf(a0, wna, a1 * wa);                                        \
        float n5 = fmaf(a2, wb,  a3 * wnb);                                       \
        float n6 = fmaf(a4, wnb, a5 * wb);                                        \
        float n7 = fmaf(a6, wa,  a7 * wna);                                       \
        float m = fmaxf(fmaxf(fmaxf(n0, n1), fmaxf(n2, n3)),                      \
                        fmaxf(fmaxf(n4, n5), fmaxf(n6, n7)));                     \
        sc = __int_as_float(0x7F000000 - (__float_as_int(m) & 0x7F800000));       \
        a0 = n0; a1 = n1; a2 = n2; a3 = n3; a4 = n4; a5 = n5; a6 = n6; a7 = n7;   \
    }

#define STEP_BWD(W)                                                               \
    {                                                                             \
        float wa = (W).x * sc, wb = (W).y * sc, wnb = (W).z * sc, wna = (W).w * sc;\
        float n0 = fmaf(wa, b0, wna * b4);                                        \
        float n1 = fmaf(wa, b4, wna * b0);                                        \
        float n2 = fmaf(wb, b5, wnb * b1);                                        \
        float n3 = fmaf(wb, b1, wnb * b5);                                        \
        float n4 = fmaf(wb, b2, wnb * b6);                                        \
        float n5 = fmaf(wb, b6, wnb * b2);                                        \
        float n6 = fmaf(wa, b7, wna * b3);                                        \
        float n7 = fmaf(wa, b3, wna * b7);                                        \
        float m = fmaxf(fmaxf(fmaxf(n0, n1), fmaxf(n2, n3)),                      \
                        fmaxf(fmaxf(n4, n5), fmaxf(n6, n7)));                     \
        sc = __int_as_float(0x7F000000 - (__float_as_int(m) & 0x7F800000));       \
        b0 = n0; b1 = n1; b2 = n2; b3 = n3; b4 = n4; b5 = n5; b6 = n6; b7 = n7;   \
    }

// ---------------- fused windowed BCJR: fwd(alpha->smem) + bwd + posterior ----------------
// 2 warps/block: warp0 = forward chain, warp1 = backward chain + posterior.
// Phase 1: fwd warm-up + steady (alpha -> smem)  ||  bwd warm-up   (concurrent warps)
// One CONVERGED __syncthreads(), then phase 2: bwd steady + posterior on warp1.
__global__ void __launch_bounds__(64, 1) k_scan(float* __restrict__ lpost) {
    __shared__ float4 sA[CH * 64];                  // [s][2][32] float4: states 0-3, 4-7
    int chunk = blockIdx.x >> 3;
    int lane  = threadIdx.x & 31;
    int b     = ((blockIdx.x & 7) << 5) | lane;
    int cbase = chunk * CH;
    int cend  = cbase + CH;
    const float4* Wp = g_W + b;

    // backward-warp persistent state (lives across the barrier)
    float b0 = 1.f, b1 = 1.f, b2 = 1.f, b3 = 1.f, b4 = 1.f, b5 = 1.f, b6 = 1.f, b7 = 1.f;
    float bsc = 1.f;
    float4 bw[8];

    if (threadIdx.x < 32) {
        // ---- phase 1, warp0: forward warm-up + steady (alpha -> smem) ----
        int kbeg = cbase - WU; if (kbeg < 0) kbeg = 0;
        float a0, a1, a2, a3, a4, a5, a6, a7;
        if (kbeg == 0) { a0 = 1.f; a1 = a2 = a3 = a4 = a5 = a6 = a7 = 0.f; }
        else           { a0 = a1 = a2 = a3 = a4 = a5 = a6 = a7 = 1.f; }
        float sc = 1.f;
        float4 w[8];
#pragma unroll
        for (int i = 0; i < 8; i++) {
            int kk = kbeg + i; kk = (kk < cend) ? kk : (cend - 1);
            w[i] = Wp[(size_t)kk * BB];
        }
#pragma unroll 1
        for (int k = kbeg; k < cbase; k += 8) {      // warm-up (len 0 or WU)
#pragma unroll
            for (int i = 0; i < 8; i++) {
                float4 W = w[i];
                int nk = k + 8 + i; nk = (nk < cend) ? nk : (cend - 1);
                w[i] = Wp[(size_t)nk * BB];
                STEP_FWD(W);
            }
        }
#pragma unroll 1
        for (int k = cbase; k < cend; k += 8) {      // steady: store alpha to smem
#pragma unroll
            for (int i = 0; i < 8; i++) {
                float4 W = w[i];
                int nk = k + 8 + i; nk = (nk < cend) ? nk : (cend - 1);
                w[i] = Wp[(size_t)nk * BB];
                int s = k + i - cbase;
                sA[s * 64 + lane]      = make_float4(a0, a1, a2, a3);
                sA[s * 64 + 32 + lane] = make_float4(a4, a5, a6, a7);
                STEP_FWD(W);
            }
        }
    } else {
        // ---- phase 1, warp1: backward warm-up ----
        int kend = cend + WU; if (kend > KK) kend = KK;
#pragma unroll
        for (int i = 0; i < 8; i++) {
            int kk = kend - 1 - i; kk = (kk >= cbase) ? kk : cbase;
            bw[i] = Wp[(size_t)kk * BB];
        }
#pragma unroll 1
        for (int k = kend - 1; k >= cend; k -= 8) {  // warm-up (len 0 or WU)
#pragma unroll
            for (int i = 0; i < 8; i++) {
                int kk = k - i;
                float4 W = bw[i];
                int pk = kk - 8; pk = (pk >= cbase) ? pk : cbase;
                bw[i] = Wp[(size_t)pk * BB];
                float sc = bsc;
                STEP_BWD(W);
                bsc = sc;
            }
        }
    }

    __syncthreads();                                 // single converged barrier

    if (threadIdx.x >= 32) {
        // ---- phase 2, warp1: backward steady + posterior ----
        float sc = bsc;
#pragma unroll 1
        for (int k = cend - 1; k >= cbase; k -= 8) {
#pragma unroll
            for (int i = 0; i < 8; i++) {
                int kk = k - i;
                float4 W = bw[i];
                int pk = kk - 8; pk = (pk >= cbase) ? pk : cbase;
                bw[i] = Wp[(size_t)pk * BB];

                int s = kk - cbase;
                float4 A1 = sA[s * 64 + lane];
                float4 A2 = sA[s * 64 + 32 + lane];
                float s0a = fmaf(A1.x, b0, fmaf(A1.y, b4, fmaf(A2.z, b7, A2.w * b3)));
                float s0b = fmaf(A1.z, b5, fmaf(A1.w, b1, fmaf(A2.x, b2, A2.y * b6)));
                float s1a = fmaf(A1.x, b4, fmaf(A1.y, b0, fmaf(A2.z, b3, A2.w * b7)));
                float s1b = fmaf(A1.z, b1, fmaf(A1.w, b5, fmaf(A2.x, b6, A2.y * b2)));
                float S0 = fmaf(W.x, s0a, W.y * s0b);
                float S1 = fmaf(W.w, s1a, W.z * s1b);
                lpost[kk * BB + b] = flog(fmaxf(S0, 1e-37f)) - flog(fmaxf(S1, 1e-37f));

                STEP_BWD(W);
            }
        }
    }
}

// ---------------- output scatter ----------------
__global__ void k_out(float* __restrict__ outp) {
    int idx = blockIdx.x * 256 + threadIdx.x;       // idx = k*BB + b
    int b = idx & (BB - 1), k = idx >> 8;
    outp[(size_t)b * KK + k] = -g_lpost2[g_inv[k] * BB + b];
}

// ---------------- launch ----------------
extern "C" void kernel_launch(void* const* d_in, const int* in_sizes, int n_in,
                              void* d_out, int out_size) {
    const float* in  = (const float*)d_in[0];
    const int* perm  = (const int*)d_in[1];
    if (n_in >= 2 && in_sizes[0] == KK && in_sizes[1] != KK) {   // defensive: swapped order
        in   = (const float*)d_in[1];
        perm = (const int*)d_in[0];
    }
    const int NB = (KK * BB) / 256;       // 6144 blocks of 256 threads
    const int NSCAN = NCH * 8;            // 1024 blocks of 64 threads

    // device-symbol addresses for lpost args (query only; capture-safe)
    float* lp1p = nullptr; float* lp2p = nullptr;
    cudaGetSymbolAddress((void**)&lp1p, g_lpost1);
    cudaGetSymbolAddress((void**)&lp2p, g_lpost2);

    k_deint<<<NB, 256>>>(in);
    k_inv<<<KK / 256, 256>>>(perm);
    k_init2<<<NB, 256>>>(perm);

    for (int it = 0; it < NITER; it++) {
        k_prep1<<<NB, 256>>>();
        k_scan<<<NSCAN, 64>>>(lp1p);
        k_prep2<<<NB, 256>>>(perm);
        k_scan<<<NSCAN, 64>>>(lp2p);
    }
    k_out<<<NB, 256>>>((float*)d_out);
}

// round 13
// speedup vs baseline: 14.8392x; 1.1391x over previous
#include <cuda_runtime.h>
#include <cuda_bf16.h>
#include <cstdint>

#define KK 6144
#define BB 256
#define NITER 6
#define CH 48                   // stored chunk length (48*64*16 = 48KB smem)
#define WU 48                   // warm-up length (multiple of 8)
#define NCH (KK / CH)           // 128 chunks

// ---------------- scratch (static __device__ — no allocations) ----------------
__device__ float4 g_W[KK * BB];            // per-step edge weights {wa, wb, wnb, wna}
__device__ float  g_ls1[KK * BB];
__device__ float  g_lp1[KK * BB];
__device__ float  g_lp2[KK * BB];
__device__ float  g_ls2[KK * BB];
__device__ float  g_la1[KK * BB];
__device__ float  g_la2[KK * BB];
__device__ float  g_lpost1[KK * BB];
__device__ float  g_lpost2[KK * BB];
__device__ int    g_inv[KK];

// ---------------- FMA-pipe exp/log (no MUFU) ----------------
__device__ __forceinline__ float fexp(float x) {
    x = fmaxf(x, -80.0f);
    float t  = fmaf(x, 1.4426950408889634f, 12582912.0f);
    int   ir = __float_as_int(t) - 0x4B400000;
    float r  = t - 12582912.0f;
    float f  = fmaf(x, 1.4426950408889634f, -r);
    float p  = 1.5403530393e-4f;
    p = fmaf(p, f, 1.3333558146e-3f);
    p = fmaf(p, f, 9.6181291076e-3f);
    p = fmaf(p, f, 5.5504108664e-2f);
    p = fmaf(p, f, 2.4022650696e-1f);
    p = fmaf(p, f, 6.9314718056e-1f);
    p = fmaf(p, f, 1.0f);
    return __int_as_float(__float_as_int(p) + (ir << 23));
}

__device__ __forceinline__ float flog(float x) {
    int bits = __float_as_int(x);
    int e    = (bits >> 23) - 126;
    float mant = __int_as_float((bits & 0x007FFFFF) | 0x3F000000);
    if (mant < 0.70710678f) { e -= 1; mant += mant; }
    float z  = mant - 1.0f;
    float zz = z * z;
    float p  = 7.0376836292e-2f;
    p = fmaf(p, z, -1.1514610310e-1f);
    p = fmaf(p, z,  1.1676998740e-1f);
    p = fmaf(p, z, -1.2420140846e-1f);
    p = fmaf(p, z,  1.4249322787e-1f);
    p = fmaf(p, z, -1.6668057665e-1f);
    p = fmaf(p, z,  2.0000714765e-1f);
    p = fmaf(p, z, -2.4999993993e-1f);
    p = fmaf(p, z,  3.3333331174e-1f);
    float y = fmaf(p * z, zz, -0.5f * zz);
    return fmaf((float)e, 0.69314718056f, z + y);
}

// ---------------- setup ----------------
__global__ void k_deint(const float* __restrict__ in) {
    int idx = blockIdx.x * 256 + threadIdx.x;       // idx = b*KK + k
    int k = idx % KK, b = idx / KK;
    const float* p = in + (size_t)b * (3 * KK) + 3 * k;
    float v0 = p[0], v1 = p[1], v2 = p[2];
    g_ls1[k * BB + b] = -v0;
    g_lp1[k * BB + b] = -v1;
    g_lp2[k * BB + b] = -v2;
}

// inv table + ls2 = ls1[perm], la2 = 0, lpost2 = ls2 (=> first la1 = 0)
__global__ void k_init2(const int* __restrict__ perm) {
    int idx = blockIdx.x * 256 + threadIdx.x;       // idx = j*BB + b
    if (idx < KK) g_inv[perm[idx]] = idx;
    int b = idx & (BB - 1), j = idx >> 8;
    float v = g_ls1[perm[j] * BB + b];
    g_ls2[idx] = v;
    g_la2[idx] = 0.0f;
    g_lpost2[idx] = v;
}

// ---------------- prep: a-priori reconstruction + gamma exponentials ----------------
// One thread handles a (k, b..b+1) pair: float2 loads, shared inv[k] gather base.
__device__ __forceinline__ float4 make_W(float lsu, float lpv) {
    float ga = 0.5f * (lsu + lpv);
    float gb = 0.5f * (lsu - lpv);
    float m  = fmaxf(fabsf(ga), fabsf(gb));
    return make_float4(fexp(ga - m), fexp(gb - m), fexp(-gb - m), fexp(-ga - m));
}

__global__ void k_prep1() {                          // build W for decoder 1
    int t = blockIdx.x * 256 + threadIdx.x;         // t indexes (k, b-pair)
    int bp = (t & 127) << 1, k = t >> 7;
    int idx = k * BB + bp;
    int jb  = g_inv[k] * BB + bp;
    float2 lpo = *(const float2*)&g_lpost2[jb];
    float2 la2 = *(const float2*)&g_la2[jb];
    float2 ls2 = *(const float2*)&g_ls2[jb];
    float2 ls1 = *(const float2*)&g_ls1[idx];
    float2 lp1 = *(const float2*)&g_lp1[idx];
    float lax = lpo.x - la2.x - ls2.x;               // le2_de[k] = X[inv[k]]
    float lay = lpo.y - la2.y - ls2.y;
    *(float2*)&g_la1[idx] = make_float2(lax, lay);
    g_W[idx]     = make_W(ls1.x + lax, lp1.x);
    g_W[idx + 1] = make_W(ls1.y + lay, lp1.y);
}

__global__ void k_prep2(const int* __restrict__ perm) { // build W for decoder 2
    int t = blockIdx.x * 256 + threadIdx.x;
    int bp = (t & 127) << 1, j = t >> 7;
    int idx = j * BB + bp;
    int kb  = perm[j] * BB + bp;
    float2 lpo = *(const float2*)&g_lpost1[kb];
    float2 la1 = *(const float2*)&g_la1[kb];
    float2 ls1 = *(const float2*)&g_ls1[kb];
    float2 ls2 = *(const float2*)&g_ls2[idx];
    float2 lp2 = *(const float2*)&g_lp2[idx];
    float lax = lpo.x - la1.x - ls1.x;               // la2[j] = le1[perm[j]]
    float lay = lpo.y - la1.y - ls1.y;
    *(float2*)&g_la2[idx] = make_float2(lax, lay);
    g_W[idx]     = make_W(ls2.x + lax, lp2.x);
    g_W[idx + 1] = make_W(ls2.y + lay, lp2.y);
}

// ---------------- trellis steps ----------------
#define STEP_FWD(W)                                                               \
    {                                                                             \
        float wa = (W).x * sc, wb = (W).y * sc, wnb = (W).z * sc, wna = (W).w * sc;\
        float n0 = fmaf(a0, wa,  a1 * wna);                                       \
        float n1 = fmaf(a2, wnb, a3 * wb);                                        \
        float n2 = fmaf(a4, wb,  a5 * wnb);                                       \
        float n3 = fmaf(a6, wna, a7 * wa);                                       \
        float n4 = fmaf(a0, wna, a1 * wa);                                        \
        float n5 = fmaf(a2, wb,  a3 * wnb);                                       \
        float n6 = fmaf(a4, wnb, a5 * wb);                                        \
        float n7 = fmaf(a6, wa,  a7 * wna);                                       \
        float m = fmaxf(fmaxf(fmaxf(n0, n1), fmaxf(n2, n3)),                      \
                        fmaxf(fmaxf(n4, n5), fmaxf(n6, n7)));                     \
        sc = __int_as_float(0x7F000000 - (__float_as_int(m) & 0x7F800000));       \
        a0 = n0; a1 = n1; a2 = n2; a3 = n3; a4 = n4; a5 = n5; a6 = n6; a7 = n7;   \
    }

#define STEP_BWD(W)                                                               \
    {                                                                             \
        float wa = (W).x * sc, wb = (W).y * sc, wnb = (W).z * sc, wna = (W).w * sc;\
        float n0 = fmaf(wa, b0, wna * b4);                                        \
        float n1 = fmaf(wa, b4, wna * b0);                                        \
        float n2 = fmaf(wb, b5, wnb * b1);                                        \
        float n3 = fmaf(wb, b1, wnb * b5);                                        \
        float n4 = fmaf(wb, b2, wnb * b6);                                        \
        float n5 = fmaf(wb, b6, wnb * b2);                                        \
        float n6 = fmaf(wa, b7, wna * b3);                                        \
        float n7 = fmaf(wa, b3, wna * b7);                                        \
        float m = fmaxf(fmaxf(fmaxf(n0, n1), fmaxf(n2, n3)),                      \
                        fmaxf(fmaxf(n4, n5), fmaxf(n6, n7)));                     \
        sc = __int_as_float(0x7F000000 - (__float_as_int(m) & 0x7F800000));       \
        b0 = n0; b1 = n1; b2 = n2; b3 = n3; b4 = n4; b5 = n5; b6 = n6; b7 = n7;   \
    }

// ---------------- fused windowed BCJR: fwd(alpha->smem) + bwd + posterior ----------------
__global__ void __launch_bounds__(64, 4) k_scan(float* __restrict__ lpost) {
    __shared__ float4 sA[CH * 64];                  // [s][2][32] float4: states 0-3, 4-7
    int chunk = blockIdx.x >> 3;
    int lane  = threadIdx.x & 31;
    int b     = ((blockIdx.x & 7) << 5) | lane;
    int cbase = chunk * CH;
    int cend  = cbase + CH;
    const float4* Wp = g_W + b;

    // backward-warp persistent state (lives across the barrier)
    float b0 = 1.f, b1 = 1.f, b2 = 1.f, b3 = 1.f, b4 = 1.f, b5 = 1.f, b6 = 1.f, b7 = 1.f;
    float bsc = 1.f;
    float4 bw[8];

    if (threadIdx.x < 32) {
        // ---- phase 1, warp0: forward warm-up + steady (alpha -> smem) ----
        int kbeg = cbase - WU; if (kbeg < 0) kbeg = 0;
        float a0, a1, a2, a3, a4, a5, a6, a7;
        if (kbeg == 0) { a0 = 1.f; a1 = a2 = a3 = a4 = a5 = a6 = a7 = 0.f; }
        else           { a0 = a1 = a2 = a3 = a4 = a5 = a6 = a7 = 1.f; }
        float sc = 1.f;
        float4 w[8];
#pragma unroll
        for (int i = 0; i < 8; i++) {
            int kk = kbeg + i; kk = (kk < cend) ? kk : (cend - 1);
            w[i] = Wp[kk * BB];
        }
#pragma unroll 1
        for (int k = kbeg; k < cbase; k += 8) {      // warm-up (len 0 or WU)
#pragma unroll
            for (int i = 0; i < 8; i++) {
                float4 W = w[i];
                int nk = k + 8 + i; nk = (nk < cend) ? nk : (cend - 1);
                w[i] = Wp[nk * BB];
                STEP_FWD(W);
            }
        }
#pragma unroll 1
        for (int k = cbase; k < cend; k += 8) {      // steady: store alpha to smem
#pragma unroll
            for (int i = 0; i < 8; i++) {
                float4 W = w[i];
                int nk = k + 8 + i; nk = (nk < cend) ? nk : (cend - 1);
                w[i] = Wp[nk * BB];
                int s = k + i - cbase;
                sA[s * 64 + lane]      = make_float4(a0, a1, a2, a3);
                sA[s * 64 + 32 + lane] = make_float4(a4, a5, a6, a7);
                STEP_FWD(W);
            }
        }
    } else {
        // ---- phase 1, warp1: backward warm-up ----
        int kend = cend + WU; if (kend > KK) kend = KK;
#pragma unroll
        for (int i = 0; i < 8; i++) {
            int kk = kend - 1 - i; kk = (kk >= cbase) ? kk : cbase;
            bw[i] = Wp[kk * BB];
        }
#pragma unroll 1
        for (int k = kend - 1; k >= cend; k -= 8) {  // warm-up (len 0 or WU)
#pragma unroll
            for (int i = 0; i < 8; i++) {
                int kk = k - i;
                float4 W = bw[i];
                int pk = kk - 8; pk = (pk >= cbase) ? pk : cbase;
                bw[i] = Wp[pk * BB];
                float sc = bsc;
                STEP_BWD(W);
                bsc = sc;
            }
        }
    }

    __syncthreads();                                 // single converged barrier

    if (threadIdx.x >= 32) {
        // ---- phase 2, warp1: backward steady + posterior ----
        float sc = bsc;
#pragma unroll 1
        for (int k = cend - 1; k >= cbase; k -= 8) {
#pragma unroll
            for (int i = 0; i < 8; i++) {
                int kk = k - i;
                float4 W = bw[i];
                int pk = kk - 8; pk = (pk >= cbase) ? pk : cbase;
                bw[i] = Wp[pk * BB];

                int s = kk - cbase;
                float4 A1 = sA[s * 64 + lane];
                float4 A2 = sA[s * 64 + 32 + lane];
                float s0a = fmaf(A1.x, b0, fmaf(A1.y, b4, fmaf(A2.z, b7, A2.w * b3)));
                float s0b = fmaf(A1.z, b5, fmaf(A1.w, b1, fmaf(A2.x, b2, A2.y * b6)));
                float s1a = fmaf(A1.x, b4, fmaf(A1.y, b0, fmaf(A2.z, b3, A2.w * b7)));
                float s1b = fmaf(A1.z, b1, fmaf(A1.w, b5, fmaf(A2.x, b6, A2.y * b2)));
                float S0 = fmaf(W.x, s0a, W.y * s0b);
                float S1 = fmaf(W.w, s1a, W.z * s1b);
                lpost[kk * BB + b] = flog(fmaxf(S0, 1e-37f)) - flog(fmaxf(S1, 1e-37f));

                STEP_BWD(W);
            }
        }
    }
}

// ---------------- output: tiled transpose with inv-gather, coalesced both sides ----------------
__global__ void k_out(float* __restrict__ outp) {
    __shared__ float tile[32][33];
    int k0 = blockIdx.x * 32;                       // output k tile
    int b0 = blockIdx.y * 32;                       // batch tile
    int tx = threadIdx.x & 31, ty = threadIdx.x >> 5;   // 256 threads: ty = 0..7
#pragma unroll
    for (int i = 0; i < 4; i++) {
        int kk = k0 + ty + 8 * i;
        tile[ty + 8 * i][tx] = g_lpost2[g_inv[kk] * BB + b0 + tx];   // coalesced row read
    }
    __syncthreads();
#pragma unroll
    for (int i = 0; i < 4; i++) {
        outp[(size_t)(b0 + ty + 8 * i) * KK + k0 + tx] = -tile[tx][ty + 8 * i];  // coalesced write
    }
}

// ---------------- launch ----------------
extern "C" void kernel_launch(void* const* d_in, const int* in_sizes, int n_in,
                              void* d_out, int out_size) {
    const float* in  = (const float*)d_in[0];
    const int* perm  = (const int*)d_in[1];
    if (n_in >= 2 && in_sizes[0] == KK && in_sizes[1] != KK) {   // defensive: swapped order
        in   = (const float*)d_in[1];
        perm = (const int*)d_in[0];
    }
    const int NB  = (KK * BB) / 256;      // 6144 blocks of 256 threads
    const int NBP = (KK * BB) / 512;      // 3072 blocks (2 elements/thread)
    const int NSCAN = NCH * 8;            // 1024 blocks of 64 threads

    float* lp1p = nullptr; float* lp2p = nullptr;
    cudaGetSymbolAddress((void**)&lp1p, g_lpost1);
    cudaGetSymbolAddress((void**)&lp2p, g_lpost2);

    k_deint<<<NB, 256>>>(in);
    k_init2<<<NB, 256>>>(perm);

    for (int it = 0; it < NITER; it++) {
        k_prep1<<<NBP, 256>>>();
        k_scan<<<NSCAN, 64>>>(lp1p);
        k_prep2<<<NBP, 256>>>(perm);
        k_scan<<<NSCAN, 64>>>(lp2p);
    }
    k_out<<<dim3(KK / 32, BB / 32), 256>>>((float*)d_out);
}

// round 14
// speedup vs baseline: 17.0539x; 1.1492x over previous
#include <cuda_runtime.h>
#include <cuda_bf16.h>
#include <cstdint>

#define KK 6144
#define BB 256
#define NITER 6
#define CH 32                   // stored chunk length (32*64*16B = 32KB smem)
#define WU 32                   // warm-up length (multiple of 8)
#define NCH (KK / CH)           // 192 chunks

// ---------------- scratch (static __device__ — no allocations) ----------------
__device__ float4 g_W[KK * BB];            // per-step edge weights {wa, wb, wnb, wna}
__device__ float  g_ls1[KK * BB];
__device__ float  g_lp1[KK * BB];
__device__ float  g_lp2[KK * BB];
__device__ float  g_ls2[KK * BB];
__device__ float  g_la1[KK * BB];
__device__ float  g_la2[KK * BB];
__device__ float  g_lpost1[KK * BB];
__device__ float  g_lpost2[KK * BB];
__device__ int    g_inv[KK];

// ---------------- FMA-pipe exp/log (no MUFU) ----------------
__device__ __forceinline__ float fexp(float x) {
    x = fmaxf(x, -80.0f);
    float t  = fmaf(x, 1.4426950408889634f, 12582912.0f);
    int   ir = __float_as_int(t) - 0x4B400000;
    float r  = t - 12582912.0f;
    float f  = fmaf(x, 1.4426950408889634f, -r);
    float p  = 1.5403530393e-4f;
    p = fmaf(p, f, 1.3333558146e-3f);
    p = fmaf(p, f, 9.6181291076e-3f);
    p = fmaf(p, f, 5.5504108664e-2f);
    p = fmaf(p, f, 2.4022650696e-1f);
    p = fmaf(p, f, 6.9314718056e-1f);
    p = fmaf(p, f, 1.0f);
    return __int_as_float(__float_as_int(p) + (ir << 23));
}

__device__ __forceinline__ float flog(float x) {
    int bits = __float_as_int(x);
    int e    = (bits >> 23) - 126;
    float mant = __int_as_float((bits & 0x007FFFFF) | 0x3F000000);
    if (mant < 0.70710678f) { e -= 1; mant += mant; }
    float z  = mant - 1.0f;
    float zz = z * z;
    float p  = 7.0376836292e-2f;
    p = fmaf(p, z, -1.1514610310e-1f);
    p = fmaf(p, z,  1.1676998740e-1f);
    p = fmaf(p, z, -1.2420140846e-1f);
    p = fmaf(p, z,  1.4249322787e-1f);
    p = fmaf(p, z, -1.6668057665e-1f);
    p = fmaf(p, z,  2.0000714765e-1f);
    p = fmaf(p, z, -2.4999993993e-1f);
    p = fmaf(p, z,  3.3333331174e-1f);
    float y = fmaf(p * z, zz, -0.5f * zz);
    return fmaf((float)e, 0.69314718056f, z + y);
}

// ---------------- setup ----------------
__global__ void k_deint(const float* __restrict__ in) {
    int idx = blockIdx.x * 256 + threadIdx.x;       // idx = b*KK + k
    int k = idx % KK, b = idx / KK;
    const float* p = in + (size_t)b * (3 * KK) + 3 * k;
    float v0 = p[0], v1 = p[1], v2 = p[2];
    g_ls1[k * BB + b] = -v0;
    g_lp1[k * BB + b] = -v1;
    g_lp2[k * BB + b] = -v2;
}

// inv table + ls2 = ls1[perm], la2 = 0, lpost2 = ls2 (=> first la1 = 0)
__global__ void k_init2(const int* __restrict__ perm) {
    int idx = blockIdx.x * 256 + threadIdx.x;       // idx = j*BB + b
    if (idx < KK) g_inv[perm[idx]] = idx;
    int b = idx & (BB - 1), j = idx >> 8;
    float v = g_ls1[perm[j] * BB + b];
    g_ls2[idx] = v;
    g_la2[idx] = 0.0f;
    g_lpost2[idx] = v;
}

// ---------------- prep: a-priori reconstruction + gamma exponentials (4-wide) ----------------
__device__ __forceinline__ float4 make_W(float lsu, float lpv) {
    float ga = 0.5f * (lsu + lpv);
    float gb = 0.5f * (lsu - lpv);
    float m  = fmaxf(fabsf(ga), fabsf(gb));
    return make_float4(fexp(ga - m), fexp(gb - m), fexp(-gb - m), fexp(-ga - m));
}

__global__ void k_prep1() {                          // build W for decoder 1
    int t = blockIdx.x * 256 + threadIdx.x;         // t indexes (k, b-quad)
    int bp = (t & 63) << 2, k = t >> 6;
    int idx = k * BB + bp;
    int jb  = g_inv[k] * BB + bp;
    float4 lpo = *(const float4*)&g_lpost2[jb];
    float4 la2 = *(const float4*)&g_la2[jb];
    float4 ls2 = *(const float4*)&g_ls2[jb];
    float4 ls1 = *(const float4*)&g_ls1[idx];
    float4 lp1 = *(const float4*)&g_lp1[idx];
    float4 la;                                       // le2_de[k] = X[inv[k]]
    la.x = lpo.x - la2.x - ls2.x;  la.y = lpo.y - la2.y - ls2.y;
    la.z = lpo.z - la2.z - ls2.z;  la.w = lpo.w - la2.w - ls2.w;
    *(float4*)&g_la1[idx] = la;
    g_W[idx]     = make_W(ls1.x + la.x, lp1.x);
    g_W[idx + 1] = make_W(ls1.y + la.y, lp1.y);
    g_W[idx + 2] = make_W(ls1.z + la.z, lp1.z);
    g_W[idx + 3] = make_W(ls1.w + la.w, lp1.w);
}

__global__ void k_prep2(const int* __restrict__ perm) { // build W for decoder 2
    int t = blockIdx.x * 256 + threadIdx.x;
    int bp = (t & 63) << 2, j = t >> 6;
    int idx = j * BB + bp;
    int kb  = perm[j] * BB + bp;
    float4 lpo = *(const float4*)&g_lpost1[kb];
    float4 la1 = *(const float4*)&g_la1[kb];
    float4 ls1 = *(const float4*)&g_ls1[kb];
    float4 ls2 = *(const float4*)&g_ls2[idx];
    float4 lp2 = *(const float4*)&g_lp2[idx];
    float4 la;                                       // la2[j] = le1[perm[j]]
    la.x = lpo.x - la1.x - ls1.x;  la.y = lpo.y - la1.y - ls1.y;
    la.z = lpo.z - la1.z - ls1.z;  la.w = lpo.w - la1.w - ls1.w;
    *(float4*)&g_la2[idx] = la;
    g_W[idx]     = make_W(ls2.x + la.x, lp2.x);
    g_W[idx + 1] = make_W(ls2.y + la.y, lp2.y);
    g_W[idx + 2] = make_W(ls2.z + la.z, lp2.z);
    g_W[idx + 3] = make_W(ls2.w + la.w, lp2.w);
}

// ---------------- trellis steps (raw weights; renorm deferred, power-2 exact) ----------------
#define STEP_FWD(W)                                                               \
    {                                                                             \
        float n0 = fmaf(a0, (W).x, a1 * (W).w);                                   \
        float n1 = fmaf(a2, (W).z, a3 * (W).y);                                   \
        float n2 = fmaf(a4, (W).y, a5 * (W).z);                                   \
        float n3 = fmaf(a6, (W).w, a7 * (W).x);                                   \
        float n4 = fmaf(a0, (W).w, a1 * (W).x);                                   \
        float n5 = fmaf(a2, (W).y, a3 * (W).z);                                   \
        float n6 = fmaf(a4, (W).z, a5 * (W).y);                                   \
        float n7 = fmaf(a6, (W).x, a7 * (W).w);                                   \
        a0 = n0; a1 = n1; a2 = n2; a3 = n3; a4 = n4; a5 = n5; a6 = n6; a7 = n7;   \
    }

#define STEP_BWD(W)                                                               \
    {                                                                             \
        float n0 = fmaf((W).x, b0, (W).w * b4);                                   \
        float n1 = fmaf((W).x, b4, (W).w * b0);                                   \
        float n2 = fmaf((W).y, b5, (W).z * b1);                                   \
        float n3 = fmaf((W).y, b1, (W).z * b5);                                   \
        float n4 = fmaf((W).y, b2, (W).z * b6);                                   \
        float n5 = fmaf((W).y, b6, (W).z * b2);                                   \
        float n6 = fmaf((W).x, b7, (W).w * b3);                                   \
        float n7 = fmaf((W).x, b3, (W).w * b7);                                   \
        b0 = n0; b1 = n1; b2 = n2; b3 = n3; b4 = n4; b5 = n5; b6 = n6; b7 = n7;   \
    }

// exact power-of-two renorm of 8 values (applied every 4 steps)
#define RENORM8(x0, x1, x2, x3, x4, x5, x6, x7)                                   \
    {                                                                             \
        float m = fmaxf(fmaxf(fmaxf(x0, x1), fmaxf(x2, x3)),                      \
                        fmaxf(fmaxf(x4, x5), fmaxf(x6, x7)));                     \
        float s = __int_as_float(0x7F000000 - (__float_as_int(m) & 0x7F800000));  \
        x0 *= s; x1 *= s; x2 *= s; x3 *= s;                                       \
        x4 *= s; x5 *= s; x6 *= s; x7 *= s;                                       \
    }

// ---------------- fused windowed BCJR: fwd(alpha->smem) + bwd + posterior ----------------
__global__ void __launch_bounds__(64, 7) k_scan(float* __restrict__ lpost) {
    __shared__ float4 sA[CH * 64];                  // [s][2][32] float4: states 0-3, 4-7
    int chunk = blockIdx.x >> 3;
    int lane  = threadIdx.x & 31;
    int b     = ((blockIdx.x & 7) << 5) | lane;
    int cbase = chunk * CH;
    int cend  = cbase + CH;
    const float4* Wp = g_W + b;

    // backward-warp persistent state (lives across the barrier)
    float b0 = 1.f, b1 = 1.f, b2 = 1.f, b3 = 1.f, b4 = 1.f, b5 = 1.f, b6 = 1.f, b7 = 1.f;
    float4 bw[8];

    if (threadIdx.x < 32) {
        // ---- phase 1, warp0: forward warm-up + steady (alpha -> smem) ----
        int kbeg = cbase - WU; if (kbeg < 0) kbeg = 0;
        float a0, a1, a2, a3, a4, a5, a6, a7;
        if (kbeg == 0) { a0 = 1.f; a1 = a2 = a3 = a4 = a5 = a6 = a7 = 0.f; }
        else           { a0 = a1 = a2 = a3 = a4 = a5 = a6 = a7 = 1.f; }
        float4 w[8];
#pragma unroll
        for (int i = 0; i < 8; i++) {
            int kk = kbeg + i; kk = (kk < cend) ? kk : (cend - 1);
            w[i] = Wp[kk * BB];
        }
#pragma unroll 1
        for (int k = kbeg; k < cbase; k += 8) {      // warm-up (len 0 or WU)
#pragma unroll
            for (int i = 0; i < 8; i++) {
                float4 W = w[i];
                int nk = k + 8 + i; nk = (nk < cend) ? nk : (cend - 1);
                w[i] = Wp[nk * BB];
                STEP_FWD(W);
                if ((i & 3) == 3) RENORM8(a0, a1, a2, a3, a4, a5, a6, a7);
            }
        }
#pragma unroll 1
        for (int k = cbase; k < cend; k += 8) {      // steady: store alpha to smem
#pragma unroll
            for (int i = 0; i < 8; i++) {
                float4 W = w[i];
                int nk = k + 8 + i; nk = (nk < cend) ? nk : (cend - 1);
                w[i] = Wp[nk * BB];
                int s = k + i - cbase;
                sA[s * 64 + lane]      = make_float4(a0, a1, a2, a3);
                sA[s * 64 + 32 + lane] = make_float4(a4, a5, a6, a7);
                STEP_FWD(W);
                if ((i & 3) == 3) RENORM8(a0, a1, a2, a3, a4, a5, a6, a7);
            }
        }
    } else {
        // ---- phase 1, warp1: backward warm-up ----
        int kend = cend + WU; if (kend > KK) kend = KK;
#pragma unroll
        for (int i = 0; i < 8; i++) {
            int kk = kend - 1 - i; kk = (kk >= cbase) ? kk : cbase;
            bw[i] = Wp[kk * BB];
        }
#pragma unroll 1
        for (int k = kend - 1; k >= cend; k -= 8) {  // warm-up (len 0 or WU)
#pragma unroll
            for (int i = 0; i < 8; i++) {
                int kk = k - i;
                float4 W = bw[i];
                int pk = kk - 8; pk = (pk >= cbase) ? pk : cbase;
                bw[i] = Wp[pk * BB];
                STEP_BWD(W);
                if ((i & 3) == 3) RENORM8(b0, b1, b2, b3, b4, b5, b6, b7);
            }
        }
    }

    __syncthreads();                                 // single converged barrier

    if (threadIdx.x >= 32) {
        // ---- phase 2, warp1: backward steady + posterior ----
#pragma unroll 1
        for (int k = cend - 1; k >= cbase; k -= 8) {
#pragma unroll
            for (int i = 0; i < 8; i++) {
                int kk = k - i;
                float4 W = bw[i];
                int pk = kk - 8; pk = (pk >= cbase) ? pk : cbase;
                bw[i] = Wp[pk * BB];

                int s = kk - cbase;
                float4 A1 = sA[s * 64 + lane];
                float4 A2 = sA[s * 64 + 32 + lane];
                float s0a = fmaf(A1.x, b0, fmaf(A1.y, b4, fmaf(A2.z, b7, A2.w * b3)));
                float s0b = fmaf(A1.z, b5, fmaf(A1.w, b1, fmaf(A2.x, b2, A2.y * b6)));
                float s1a = fmaf(A1.x, b4, fmaf(A1.y, b0, fmaf(A2.z, b3, A2.w * b7)));
                float s1b = fmaf(A1.z, b1, fmaf(A1.w, b5, fmaf(A2.x, b6, A2.y * b2)));
                float S0 = fmaf(W.x, s0a, W.y * s0b);
                float S1 = fmaf(W.w, s1a, W.z * s1b);
                lpost[kk * BB + b] = flog(fmaxf(S0, 1e-37f)) - flog(fmaxf(S1, 1e-37f));

                STEP_BWD(W);
                if ((i & 3) == 3) RENORM8(b0, b1, b2, b3, b4, b5, b6, b7);
            }
        }
    }
}

// ---------------- output: tiled transpose with inv-gather, coalesced both sides ----------------
__global__ void k_out(float* __restrict__ outp) {
    __shared__ float tile[32][33];
    int k0 = blockIdx.x * 32;                       // output k tile
    int b0 = blockIdx.y * 32;                       // batch tile
    int tx = threadIdx.x & 31, ty = threadIdx.x >> 5;   // 256 threads: ty = 0..7
#pragma unroll
    for (int i = 0; i < 4; i++) {
        int kk = k0 + ty + 8 * i;
        tile[ty + 8 * i][tx] = g_lpost2[g_inv[kk] * BB + b0 + tx];   // coalesced row read
    }
    __syncthreads();
#pragma unroll
    for (int i = 0; i < 4; i++) {
        outp[(size_t)(b0 + ty + 8 * i) * KK + k0 + tx] = -tile[tx][ty + 8 * i];  // coalesced write
    }
}

// ---------------- launch ----------------
extern "C" void kernel_launch(void* const* d_in, const int* in_sizes, int n_in,
                              void* d_out, int out_size) {
    const float* in  = (const float*)d_in[0];
    const int* perm  = (const int*)d_in[1];
    if (n_in >= 2 && in_sizes[0] == KK && in_sizes[1] != KK) {   // defensive: swapped order
        in   = (const float*)d_in[1];
        perm = (const int*)d_in[0];
    }
    const int NB   = (KK * BB) / 256;     // 6144 blocks of 256 threads
    const int NBP4 = (KK * BB) / 1024;    // 1536 blocks (4 elements/thread)
    const int NSCAN = NCH * 8;            // 1536 blocks of 64 threads

    float* lp1p = nullptr; float* lp2p = nullptr;
    cudaGetSymbolAddress((void**)&lp1p, g_lpost1);
    cudaGetSymbolAddress((void**)&lp2p, g_lpost2);

    k_deint<<<NB, 256>>>(in);
    k_init2<<<NB, 256>>>(perm);

    for (int it = 0; it < NITER; it++) {
        k_prep1<<<NBP4, 256>>>();
        k_scan<<<NSCAN, 64>>>(lp1p);
        k_prep2<<<NBP4, 256>>>(perm);
        k_scan<<<NSCAN, 64>>>(lp2p);
    }
    k_out<<<dim3(KK / 32, BB / 32), 256>>>((float*)d_out);
}

// round 16
// speedup vs baseline: 18.9215x; 1.1095x over previous
#include <cuda_runtime.h>
#include <cuda_bf16.h>
#include <cstdint>

#define KK 6144
#define BB 256
#define NITER 6
#define CH 32                   // chunk length
#define HF 16                   // half chunk
#define WU 32                   // warm-up length (multiple of 8)
#define NCH (KK / CH)           // 192 chunks

// ---------------- scratch (static __device__ — no allocations) ----------------
__device__ float4 g_W[KK * BB];            // per-step edge weights {wa, wb, wnb, wna}
__device__ float  g_ls1[KK * BB];
__device__ float  g_lp1[KK * BB];
__device__ float  g_lp2[KK * BB];
__device__ float  g_ls2[KK * BB];
__device__ float  g_la1[KK * BB];
__device__ float  g_la2[KK * BB];
__device__ float2 g_S1[KK * BB];           // decoder-1 posterior pair (S0, S1)
__device__ float2 g_S2[KK * BB];           // decoder-2 posterior pair (S0, S1)
__device__ int    g_inv[KK];

// ---------------- FMA-pipe exp/log (no MUFU) ----------------
__device__ __forceinline__ float fexp(float x) {
    x = fmaxf(x, -80.0f);
    float t  = fmaf(x, 1.4426950408889634f, 12582912.0f);
    int   ir = __float_as_int(t) - 0x4B400000;
    float r  = t - 12582912.0f;
    float f  = fmaf(x, 1.4426950408889634f, -r);
    float p  = 1.5403530393e-4f;
    p = fmaf(p, f, 1.3333558146e-3f);
    p = fmaf(p, f, 9.6181291076e-3f);
    p = fmaf(p, f, 5.5504108664e-2f);
    p = fmaf(p, f, 2.4022650696e-1f);
    p = fmaf(p, f, 6.9314718056e-1f);
    p = fmaf(p, f, 1.0f);
    return __int_as_float(__float_as_int(p) + (ir << 23));
}

__device__ __forceinline__ float flog(float x) {
    int bits = __float_as_int(x);
    int e    = (bits >> 23) - 126;
    float mant = __int_as_float((bits & 0x007FFFFF) | 0x3F000000);
    if (mant < 0.70710678f) { e -= 1; mant += mant; }
    float z  = mant - 1.0f;
    float zz = z * z;
    float p  = 7.0376836292e-2f;
    p = fmaf(p, z, -1.1514610310e-1f);
    p = fmaf(p, z,  1.1676998740e-1f);
    p = fmaf(p, z, -1.2420140846e-1f);
    p = fmaf(p, z,  1.4249322787e-1f);
    p = fmaf(p, z, -1.6668057665e-1f);
    p = fmaf(p, z,  2.0000714765e-1f);
    p = fmaf(p, z, -2.4999993993e-1f);
    p = fmaf(p, z,  3.3333331174e-1f);
    float y = fmaf(p * z, zz, -0.5f * zz);
    return fmaf((float)e, 0.69314718056f, z + y);
}

// posterior LLR from stored pair
__device__ __forceinline__ float lpair(float2 s) {
    return flog(fmaxf(s.x, 1e-37f)) - flog(fmaxf(s.y, 1e-37f));
}

// ---------------- setup ----------------
__global__ void k_deint(const float* __restrict__ in) {
    int idx = blockIdx.x * 256 + threadIdx.x;       // idx = b*KK + k
    int k = idx % KK, b = idx / KK;
    const float* p = in + (size_t)b * (3 * KK) + 3 * k;
    float v0 = p[0], v1 = p[1], v2 = p[2];
    g_ls1[k * BB + b] = -v0;
    g_lp1[k * BB + b] = -v1;
    g_lp2[k * BB + b] = -v2;
}

// inv table + ls2 = ls1[perm], la2 = 0, S2 pair s.t. lpost2 == ls2 (=> first la1 = 0)
__global__ void k_init2(const int* __restrict__ perm) {
    int idx = blockIdx.x * 256 + threadIdx.x;       // idx = j*BB + b
    if (idx < KK) g_inv[perm[idx]] = idx;
    int b = idx & (BB - 1), j = idx >> 8;
    float v = g_ls1[perm[j] * BB + b];
    g_ls2[idx] = v;
    g_la2[idx] = 0.0f;
    g_S2[idx] = make_float2(fexp(v), 1.0f);
}

// ---------------- prep: a-priori reconstruction + gamma exponentials (4-wide) ----------------
__device__ __forceinline__ float4 make_W(float lsu, float lpv) {
    float ga = 0.5f * (lsu + lpv);
    float gb = 0.5f * (lsu - lpv);
    float m  = fmaxf(fabsf(ga), fabsf(gb));
    return make_float4(fexp(ga - m), fexp(gb - m), fexp(-gb - m), fexp(-ga - m));
}

__global__ void k_prep1() {                          // build W for decoder 1
    int t = blockIdx.x * 256 + threadIdx.x;         // t indexes (k, b-quad)
    int bp = (t & 63) << 2, k = t >> 6;
    int idx = k * BB + bp;
    int jb  = g_inv[k] * BB + bp;
    float2 s0 = g_S2[jb],  s1 = g_S2[jb + 1], s2 = g_S2[jb + 2], s3 = g_S2[jb + 3];
    float4 la2 = *(const float4*)&g_la2[jb];
    float4 ls2 = *(const float4*)&g_ls2[jb];
    float4 ls1 = *(const float4*)&g_ls1[idx];
    float4 lp1 = *(const float4*)&g_lp1[idx];
    float4 la;                                       // le2_de[k] = X[inv[k]]
    la.x = lpair(s0) - la2.x - ls2.x;  la.y = lpair(s1) - la2.y - ls2.y;
    la.z = lpair(s2) - la2.z - ls2.z;  la.w = lpair(s3) - la2.w - ls2.w;
    *(float4*)&g_la1[idx] = la;
    g_W[idx]     = make_W(ls1.x + la.x, lp1.x);
    g_W[idx + 1] = make_W(ls1.y + la.y, lp1.y);
    g_W[idx + 2] = make_W(ls1.z + la.z, lp1.z);
    g_W[idx + 3] = make_W(ls1.w + la.w, lp1.w);
}

__global__ void k_prep2(const int* __restrict__ perm) { // build W for decoder 2
    int t = blockIdx.x * 256 + threadIdx.x;
    int bp = (t & 63) << 2, j = t >> 6;
    int idx = j * BB + bp;
    int kb  = perm[j] * BB + bp;
    float2 s0 = g_S1[kb],  s1 = g_S1[kb + 1], s2 = g_S1[kb + 2], s3 = g_S1[kb + 3];
    float4 la1 = *(const float4*)&g_la1[kb];
    float4 ls1 = *(const float4*)&g_ls1[kb];
    float4 ls2 = *(const float4*)&g_ls2[idx];
    float4 lp2 = *(const float4*)&g_lp2[idx];
    float4 la;                                       // la2[j] = le1[perm[j]]
    la.x = lpair(s0) - la1.x - ls1.x;  la.y = lpair(s1) - la1.y - ls1.y;
    la.z = lpair(s2) - la1.z - ls1.z;  la.w = lpair(s3) - la1.w - ls1.w;
    *(float4*)&g_la2[idx] = la;
    g_W[idx]     = make_W(ls2.x + la.x, lp2.x);
    g_W[idx + 1] = make_W(ls2.y + la.y, lp2.y);
    g_W[idx + 2] = make_W(ls2.z + la.z, lp2.z);
    g_W[idx + 3] = make_W(ls2.w + la.w, lp2.w);
}

// ---------------- trellis steps (raw weights; renorm deferred, power-2 exact) ----------------
#define STEP_FWD(W)                                                               \
    {                                                                             \
        float n0 = fmaf(a0, (W).x, a1 * (W).w);                                   \
        float n1 = fmaf(a2, (W).z, a3 * (W).y);                                   \
        float n2 = fmaf(a4, (W).y, a5 * (W).z);                                   \
        float n3 = fmaf(a6, (W).w, a7 * (W).x);                                   \
        float n4 = fmaf(a0, (W).w, a1 * (W).x);                                   \
        float n5 = fmaf(a2, (W).y, a3 * (W).z);                                   \
        float n6 = fmaf(a4, (W).z, a5 * (W).y);                                   \
        float n7 = fmaf(a6, (W).x, a7 * (W).w);                                   \
        a0 = n0; a1 = n1; a2 = n2; a3 = n3; a4 = n4; a5 = n5; a6 = n6; a7 = n7;   \
    }

#define STEP_BWD(W)                                                               \
    {                                                                             \
        float n0 = fmaf((W).x, b0, (W).w * b4);                                   \
        float n1 = fmaf((W).x, b4, (W).w * b0);                                   \
        float n2 = fmaf((W).y, b5, (W).z * b1);                                   \
        float n3 = fmaf((W).y, b1, (W).z * b5);                                   \
        float n4 = fmaf((W).y, b2, (W).z * b6);                                   \
        float n5 = fmaf((W).y, b6, (W).z * b2);                                   \
        float n6 = fmaf((W).x, b7, (W).w * b3);                                   \
        float n7 = fmaf((W).x, b3, (W).w * b7);                                   \
        b0 = n0; b1 = n1; b2 = n2; b3 = n3; b4 = n4; b5 = n5; b6 = n6; b7 = n7;   \
    }

#define RENORM8(x0, x1, x2, x3, x4, x5, x6, x7)                                   \
    {                                                                             \
        float m = fmaxf(fmaxf(fmaxf(x0, x1), fmaxf(x2, x3)),                      \
                        fmaxf(fmaxf(x4, x5), fmaxf(x6, x7)));                     \
        float s = __int_as_float(0x7F000000 - (__float_as_int(m) & 0x7F800000));  \
        x0 *= s; x1 *= s; x2 *= s; x3 *= s;                                       \
        x4 *= s; x5 *= s; x6 *= s; x7 *= s;                                       \
    }

// ---------------- balanced fused windowed BCJR ----------------
// warp0: fwd warm(WU) + steady store alpha [cbase,cmid) ; after barrier: fwd+posterior [cmid,cend)
// warp1: bwd warm(WU) + steady store beta  [cmid,cend)  ; after barrier: bwd+posterior [cbase,cmid)
__global__ void __launch_bounds__(64, 7) k_scan(float2* __restrict__ Sout) {
    __shared__ float4 sA[HF * 64];                  // alpha_k for k in [cbase, cmid)
    __shared__ float4 sB[HF * 64];                  // beta_{k+1} for k in [cmid, cend)
    int chunk = blockIdx.x >> 3;
    int lane  = threadIdx.x & 31;
    int b     = ((blockIdx.x & 7) << 5) | lane;
    int cbase = chunk * CH;
    int cmid  = cbase + HF;
    int cend  = cbase + CH;
    const float4* Wp = g_W + b;

    // per-warp persistent state (live across the barrier)
    float a0, a1, a2, a3, a4, a5, a6, a7;            // warp0: alpha
    float b0, b1, b2, b3, b4, b5, b6, b7;            // warp1: beta
    float4 w[8];

    if (threadIdx.x < 32) {
        // ---- phase 1, warp0 ----
        int kbeg = cbase - WU; if (kbeg < 0) kbeg = 0;
        if (kbeg == 0) { a0 = 1.f; a1 = a2 = a3 = a4 = a5 = a6 = a7 = 0.f; }
        else           { a0 = a1 = a2 = a3 = a4 = a5 = a6 = a7 = 1.f; }
#pragma unroll
        for (int i = 0; i < 8; i++) {
            int kk = kbeg + i; kk = (kk < cend) ? kk : (cend - 1);
            w[i] = Wp[kk * BB];
        }
#pragma unroll 1
        for (int k = kbeg; k < cbase; k += 8) {      // warm-up (0 or WU steps)
#pragma unroll
            for (int i = 0; i < 8; i++) {
                float4 W = w[i];
                int nk = k + 8 + i; nk = (nk < cend) ? nk : (cend - 1);
                w[i] = Wp[nk * BB];
                STEP_FWD(W);
                if ((i & 3) == 3) RENORM8(a0, a1, a2, a3, a4, a5, a6, a7);
            }
        }
#pragma unroll 1
        for (int k = cbase; k < cmid; k += 8) {      // steady: store alpha_k
#pragma unroll
            for (int i = 0; i < 8; i++) {
                float4 W = w[i];
                int nk = k + 8 + i; nk = (nk < cend) ? nk : (cend - 1);
                w[i] = Wp[nk * BB];
                int s = k + i - cbase;
                sA[s * 64 + lane]      = make_float4(a0, a1, a2, a3);
                sA[s * 64 + 32 + lane] = make_float4(a4, a5, a6, a7);
                STEP_FWD(W);
                if ((i & 3) == 3) RENORM8(a0, a1, a2, a3, a4, a5, a6, a7);
            }
        }
    } else {
        // ---- phase 1, warp1 ----
        int kend = cend + WU; if (kend > KK) kend = KK;
        b0 = b1 = b2 = b3 = b4 = b5 = b6 = b7 = 1.f;
#pragma unroll
        for (int i = 0; i < 8; i++) {
            int kk = kend - 1 - i; kk = (kk >= cbase) ? kk : cbase;
            w[i] = Wp[kk * BB];
        }
#pragma unroll 1
        for (int k = kend - 1; k >= cend; k -= 8) {  // warm-up (0 or WU steps)
#pragma unroll
            for (int i = 0; i < 8; i++) {
                int kk = k - i;
                float4 W = w[i];
                int pk = kk - 8; pk = (pk >= cbase) ? pk : cbase;
                w[i] = Wp[pk * BB];
                STEP_BWD(W);
                if ((i & 3) == 3) RENORM8(b0, b1, b2, b3, b4, b5, b6, b7);
            }
        }
#pragma unroll 1
        for (int k = cend - 1; k >= cmid; k -= 8) {  // steady: store beta_{k+1}
#pragma unroll
            for (int i = 0; i < 8; i++) {
                int kk = k - i;
                float4 W = w[i];
                int pk = kk - 8; pk = (pk >= cbase) ? pk : cbase;
                w[i] = Wp[pk * BB];
                int s = kk - cmid;
                sB[s * 64 + lane]      = make_float4(b0, b1, b2, b3);
                sB[s * 64 + 32 + lane] = make_float4(b4, b5, b6, b7);
                STEP_BWD(W);
                if ((i & 3) == 3) RENORM8(b0, b1, b2, b3, b4, b5, b6, b7);
            }
        }
    }

    __syncthreads();                                 // single converged barrier

    if (threadIdx.x < 32) {
        // ---- phase 2, warp0: fwd + posterior for k in [cmid, cend) ----
#pragma unroll 1
        for (int k = cmid; k < cend; k += 8) {
#pragma unroll
            for (int i = 0; i < 8; i++) {
                float4 W = w[i];
                int nk = k + 8 + i; nk = (nk < cend) ? nk : (cend - 1);
                w[i] = Wp[nk * BB];
                int s = k + i - cmid;
                float4 B1 = sB[s * 64 + lane];       // beta_{k+1} states 0-3
                float4 B2 = sB[s * 64 + 32 + lane];  // states 4-7
                float s0a = fmaf(a0, B1.x, fmaf(a1, B2.x, fmaf(a6, B2.w, a7 * B1.w)));
                float s0b = fmaf(a2, B2.y, fmaf(a3, B1.y, fmaf(a4, B1.z, a5 * B2.z)));
                float s1a = fmaf(a0, B2.x, fmaf(a1, B1.x, fmaf(a6, B1.w, a7 * B2.w)));
                float s1b = fmaf(a2, B1.y, fmaf(a3, B2.y, fmaf(a4, B2.z, a5 * B1.z)));
                float S0 = fmaf(W.x, s0a, W.y * s0b);
                float S1 = fmaf(W.w, s1a, W.z * s1b);
                Sout[(k + i) * BB + b] = make_float2(S0, S1);
                STEP_FWD(W);
                if ((i & 3) == 3) RENORM8(a0, a1, a2, a3, a4, a5, a6, a7);
            }
        }
    } else {
        // ---- phase 2, warp1: bwd + posterior for k in [cbase, cmid) ----
#pragma unroll 1
        for (int k = cmid - 1; k >= cbase; k -= 8) {
#pragma unroll
            for (int i = 0; i < 8; i++) {
                int kk = k - i;
                float4 W = w[i];
                int pk = kk - 8; pk = (pk >= cbase) ? pk : cbase;
                w[i] = Wp[pk * BB];
                int s = kk - cbase;
                float4 A1 = sA[s * 64 + lane];       // alpha_kk states 0-3
                float4 A2 = sA[s * 64 + 32 + lane];  // states 4-7
                float s0a = fmaf(A1.x, b0, fmaf(A1.y, b4, fmaf(A2.z, b7, A2.w * b3)));
                float s0b = fmaf(A1.z, b5, fmaf(A1.w, b1, fmaf(A2.x, b2, A2.y * b6)));
                float s1a = fmaf(A1.x, b4, fmaf(A1.y, b0, fmaf(A2.z, b3, A2.w * b7)));
                float s1b = fmaf(A1.z, b1, fmaf(A1.w, b5, fmaf(A2.x, b6, A2.y * b2)));
                float S0 = fmaf(W.x, s0a, W.y * s0b);
                float S1 = fmaf(W.w, s1a, W.z * s1b);
                Sout[kk * BB + b] = make_float2(S0, S1);
                STEP_BWD(W);
                if ((i & 3) == 3) RENORM8(b0, b1, b2, b3, b4, b5, b6, b7);
            }
        }
    }
}

// ---------------- output: tiled transpose with inv-gather, coalesced both sides ----------------
__global__ void k_out(float* __restrict__ outp) {
    __shared__ float tile[32][33];
    int k0 = blockIdx.x * 32;                       // output k tile
    int b0 = blockIdx.y * 32;                       // batch tile
    int tx = threadIdx.x & 31, ty = threadIdx.x >> 5;   // 256 threads: ty = 0..7
#pragma unroll
    for (int i = 0; i < 4; i++) {
        int kk = k0 + ty + 8 * i;
        tile[ty + 8 * i][tx] = lpair(g_S2[g_inv[kk] * BB + b0 + tx]);   // coalesced read
    }
    __syncthreads();
#pragma unroll
    for (int i = 0; i < 4; i++) {
        outp[(size_t)(b0 + ty + 8 * i) * KK + k0 + tx] = -tile[tx][ty + 8 * i];  // coalesced write
    }
}

// ---------------- launch ----------------
extern "C" void kernel_launch(void* const* d_in, const int* in_sizes, int n_in,
                              void* d_out, int out_size) {
    const float* in  = (const float*)d_in[0];
    const int* perm  = (const int*)d_in[1];
    if (n_in >= 2 && in_sizes[0] == KK && in_sizes[1] != KK) {   // defensive: swapped order
        in   = (const float*)d_in[1];
        perm = (const int*)d_in[0];
    }
    const int NB   = (KK * BB) / 256;     // 6144 blocks of 256 threads
    const int NBP4 = (KK * BB) / 1024;    // 1536 blocks (4 elements/thread)
    const int NSCAN = NCH * 8;            // 1536 blocks of 64 threads

    float2* s1p = nullptr; float2* s2p = nullptr;
    cudaGetSymbolAddress((void**)&s1p, g_S1);
    cudaGetSymbolAddress((void**)&s2p, g_S2);

    k_deint<<<NB, 256>>>(in);
    k_init2<<<NB, 256>>>(perm);

    for (int it = 0; it < NITER; it++) {
        k_prep1<<<NBP4, 256>>>();
        k_scan<<<NSCAN, 64>>>(s1p);
        k_prep2<<<NBP4, 256>>>(perm);
        k_scan<<<NSCAN, 64>>>(s2p);
    }
    k_out<<<dim3(KK / 32, BB / 32), 256>>>((float*)d_out);
}